// round 3
// baseline (speedup 1.0000x reference)
#include <cuda_runtime.h>

// ---------------- problem constants ----------------
constexpr int B_   = 8;
constexpr int T_   = 2048;
constexpr int D_   = 256;
constexpr int H_   = 4;
constexpr int HD_  = 64;
constexpr int BH_  = B_ * H_;     // 32
constexpr int NTOK_ = B_ * T_;    // 16384
constexpr float SCALE_INV = 0.125f;   // 1/sqrt(64)
constexpr float NEGINF = -1e9f;

constexpr int QT   = 16;    // queries per attention block
constexpr int SMAX = 256;   // compacted support capacity per row (dense fallback if exceeded)

// ---------------- scratch (device globals; no allocation allowed) ----------------
__device__ float g_Q[BH_ * T_ * HD_];     // [bh][t][hd]
__device__ float g_K[BH_ * T_ * HD_];
__device__ float g_V[BH_ * T_ * HD_];
__device__ float g_attn[NTOK_ * D_];      // [token][feature] (b,t,h,hd)
__device__ float g_y[NTOK_ * D_];         // pre-LN output
__device__ float g_maskf[NTOK_];          // 0.0 / 1.0
__device__ int   g_flag;                  // mask dtype: 0=u8, 1=i32, 2=f32

// ---------------- helpers ----------------
__device__ __forceinline__ float wsum(float v) {
    #pragma unroll
    for (int o = 16; o > 0; o >>= 1) v += __shfl_xor_sync(0xffffffffu, v, o);
    return v;
}
__device__ __forceinline__ int wsumi(int v) {
    #pragma unroll
    for (int o = 16; o > 0; o >>= 1) v += __shfl_xor_sync(0xffffffffu, v, o);
    return v;
}

// ---- packed f32x2 (Blackwell): 2 FMAs per fma-pipe instruction slot ----
__device__ __forceinline__ unsigned long long bcast2(float v) {
    unsigned long long r; unsigned int u = __float_as_uint(v);
    asm("mov.b64 %0, {%1, %2};" : "=l"(r) : "r"(u), "r"(u));
    return r;
}
__device__ __forceinline__ void fma2(unsigned long long& d,
                                     unsigned long long a,
                                     unsigned long long b) {
    asm("fma.rn.f32x2 %0, %1, %2, %0;" : "+l"(d) : "l"(a), "l"(b));
}
__device__ __forceinline__ float2 unpack2(unsigned long long p) {
    unsigned int lo, hi;
    asm("mov.b64 {%0, %1}, %2;" : "=r"(lo), "=r"(hi) : "l"(p));
    return make_float2(__uint_as_float(lo), __uint_as_float(hi));
}

// ---------------- mask dtype detection + normalization ----------------
// Word signatures: f32 one = 0x3f800000; i32 words are 0/1; u8-packed words
// contain bytes at offsets 1..3 -> values > 1. Mutually exclusive w.h.p.
__global__ void detect_mask_kernel(const unsigned int* __restrict__ m) {
    __shared__ int sawF, sawBig;
    if (threadIdx.x == 0) { sawF = 0; sawBig = 0; }
    __syncthreads();
    int f = 0, big = 0;
    for (int i = threadIdx.x; i < 4096; i += blockDim.x) {
        unsigned int w = m[i];
        if (w == 0x3f800000u) f = 1;
        else if (w > 1u) big = 1;
    }
    if (f)   atomicOr(&sawF, 1);
    if (big) atomicOr(&sawBig, 1);
    __syncthreads();
    if (threadIdx.x == 0) g_flag = sawF ? 2 : (sawBig ? 0 : 1);
}

__global__ void expand_mask_kernel(const void* __restrict__ m) {
    int i = blockIdx.x * blockDim.x + threadIdx.x;
    if (i >= NTOK_) return;
    int mode = g_flag;
    int v;
    if (mode == 0)      v = (((const unsigned char*)m)[i] != 0);
    else if (mode == 1) v = (((const int*)m)[i] != 0);
    else                v = (((const float*)m)[i] != 0.0f);
    g_maskf[i] = v ? 1.0f : 0.0f;
}

// ---------------- QKV GEMM (fused via blockIdx.z): C = x @ W^T -> head layout ----------
__global__ __launch_bounds__(256, 2)
void qkv_gemm_kernel(const float* __restrict__ A,
                     const float* __restrict__ Wq,
                     const float* __restrict__ Wk,
                     const float* __restrict__ Wv)
{
    __shared__ float sA[16 * 64];   // [k][m]
    __shared__ float sB[16 * 64];   // [k][n]

    const float* W   = (blockIdx.z == 0) ? Wq : (blockIdx.z == 1) ? Wk : Wv;
    float*       dst = (blockIdx.z == 0) ? g_Q : (blockIdx.z == 1) ? g_K : g_V;

    int t  = threadIdx.x;           // 256 threads
    int tx = t & 15, ty = t >> 4;
    int m0 = blockIdx.x * 64, n0 = blockIdx.y * 64;
    int lr = t >> 2, lk = t & 3;    // loader: row 0..63, k-quad 0..3

    float acc[4][4] = {};
    for (int k0 = 0; k0 < 256; k0 += 16) {
        float4 av = *(const float4*)&A[(m0 + lr) * 256 + k0 + lk * 4];
        float4 bv = *(const float4*)&W[(n0 + lr) * 256 + k0 + lk * 4];
        __syncthreads();
        sA[(lk*4+0)*64 + lr] = av.x; sA[(lk*4+1)*64 + lr] = av.y;
        sA[(lk*4+2)*64 + lr] = av.z; sA[(lk*4+3)*64 + lr] = av.w;
        sB[(lk*4+0)*64 + lr] = bv.x; sB[(lk*4+1)*64 + lr] = bv.y;
        sB[(lk*4+2)*64 + lr] = bv.z; sB[(lk*4+3)*64 + lr] = bv.w;
        __syncthreads();
        #pragma unroll
        for (int kk = 0; kk < 16; kk++) {
            float4 a4 = *(const float4*)&sA[kk * 64 + ty * 4];
            float4 b4 = *(const float4*)&sB[kk * 64 + tx * 4];
            float ar[4] = {a4.x, a4.y, a4.z, a4.w};
            float br[4] = {b4.x, b4.y, b4.z, b4.w};
            #pragma unroll
            for (int i = 0; i < 4; i++)
                #pragma unroll
                for (int j = 0; j < 4; j++)
                    acc[i][j] += ar[i] * br[j];
        }
    }

    #pragma unroll
    for (int i = 0; i < 4; i++) {
        int gm = m0 + ty * 4 + i;
        int b  = gm >> 11, tl = gm & 2047;
        #pragma unroll
        for (int j = 0; j < 4; j++) {
            int gn = n0 + tx * 4 + j;
            int h = gn >> 6, hd = gn & 63;
            dst[((b * H_ + h) * T_ + tl) * HD_ + hd] = acc[i][j];
        }
    }
}

// ---------------- out-proj GEMM: g_y = g_attn @ Wo^T + resid ----------------
__global__ __launch_bounds__(256, 2)
void oproj_gemm_kernel(const float* __restrict__ W,
                       const float* __restrict__ resid)
{
    __shared__ float sA[16 * 64];
    __shared__ float sB[16 * 64];
    const float* A = g_attn;

    int t  = threadIdx.x;
    int tx = t & 15, ty = t >> 4;
    int m0 = blockIdx.x * 64, n0 = blockIdx.y * 64;
    int lr = t >> 2, lk = t & 3;

    float acc[4][4] = {};
    for (int k0 = 0; k0 < 256; k0 += 16) {
        float4 av = *(const float4*)&A[(m0 + lr) * 256 + k0 + lk * 4];
        float4 bv = *(const float4*)&W[(n0 + lr) * 256 + k0 + lk * 4];
        __syncthreads();
        sA[(lk*4+0)*64 + lr] = av.x; sA[(lk*4+1)*64 + lr] = av.y;
        sA[(lk*4+2)*64 + lr] = av.z; sA[(lk*4+3)*64 + lr] = av.w;
        sB[(lk*4+0)*64 + lr] = bv.x; sB[(lk*4+1)*64 + lr] = bv.y;
        sB[(lk*4+2)*64 + lr] = bv.z; sB[(lk*4+3)*64 + lr] = bv.w;
        __syncthreads();
        #pragma unroll
        for (int kk = 0; kk < 16; kk++) {
            float4 a4 = *(const float4*)&sA[kk * 64 + ty * 4];
            float4 b4 = *(const float4*)&sB[kk * 64 + tx * 4];
            float ar[4] = {a4.x, a4.y, a4.z, a4.w};
            float br[4] = {b4.x, b4.y, b4.z, b4.w};
            #pragma unroll
            for (int i = 0; i < 4; i++)
                #pragma unroll
                for (int j = 0; j < 4; j++)
                    acc[i][j] += ar[i] * br[j];
        }
    }

    #pragma unroll
    for (int i = 0; i < 4; i++) {
        int gm = m0 + ty * 4 + i;
        #pragma unroll
        for (int j = 0; j < 4; j++) {
            int gn = n0 + tx * 4 + j;
            g_y[gm * 256 + gn] = acc[i][j] + resid[gm * 256 + gn];
        }
    }
}

// ---------------- fused attention: scores -> sparsemax -> sparse A@V ----------------
// grid (T/QT, BH), 512 threads. Scores tile SMEM-resident, never touches HBM.
// Phase 1 uses packed fma.rn.f32x2: Q stored as q-pairs [d][qp], K broadcast-packed.
constexpr int ATTN_SMEM =
    (QT * T_ + QT * HD_ + QT * SMAX) * 4 + (QT * SMAX + QT) * 4;

__global__ __launch_bounds__(512, 1)
void attn_kernel() {
    extern __shared__ float smem[];
    float* sS   = smem;                        // [QT][T]  scores -> p
    float* sQf  = sS + QT * T_;                // [HD][QT/2] float2 q-pairs (4 KB)
    float* sP   = sQf + QT * HD_;              // [QT][SMAX] compacted p
    int*   sIdx = (int*)(sP + QT * SMAX);      // [QT][SMAX] compacted k
    int*   sCnt = sIdx + QT * SMAX;            // [QT]
    unsigned long long* sQp = (unsigned long long*)sQf;   // [HD][8] packed pairs

    const int tid = threadIdx.x;
    const int bh  = blockIdx.y;
    const int b   = bh >> 2;
    const int h   = bh & 3;
    const int q0  = blockIdx.x * QT;

    // ---- load Q tile, transposed+paired: sQp[d][q/2] = (Q[q][d], Q[q+1][d]) ----
    const float* Qbase = g_Q + (bh * T_ + q0) * HD_;
    for (int i = tid; i < QT * HD_; i += 512) {
        int q = i >> 6, d = i & 63;
        sQf[(d * 8 + (q >> 1)) * 2 + (q & 1)] = Qbase[i];
    }
    __syncthreads();

    // ---- phase 1: scores = QK^T/8 with mask, FFMA2 inner loop ----
    const float* Kbase = g_K + bh * T_ * HD_;
    const float* mrow  = g_maskf + b * T_;
    #pragma unroll
    for (int kk = 0; kk < 2; kk++) {
        int kA = kk * 1024 + tid;           // and kA+512
        unsigned long long acc[2][8];
        #pragma unroll
        for (int j = 0; j < 8; j++) { acc[0][j] = 0ull; acc[1][j] = 0ull; }
        const float4* KrA = (const float4*)(Kbase + kA * HD_);
        const float4* KrB = (const float4*)(Kbase + (kA + 512) * HD_);
        #pragma unroll
        for (int d4 = 0; d4 < 16; d4++) {
            float4 ka = KrA[d4];
            float4 kb = KrB[d4];
            float kas[4] = {ka.x, ka.y, ka.z, ka.w};
            float kbs[4] = {kb.x, kb.y, kb.z, kb.w};
            #pragma unroll
            for (int dd = 0; dd < 4; dd++) {
                int d = d4 * 4 + dd;
                unsigned long long ba = bcast2(kas[dd]);
                unsigned long long bb = bcast2(kbs[dd]);
                const ulonglong2* qrow = (const ulonglong2*)(sQp + d * 8);
                #pragma unroll
                for (int j = 0; j < 4; j++) {
                    ulonglong2 qq = qrow[j];      // 2 q-pairs, warp-broadcast LDS.128
                    fma2(acc[0][2*j],     qq.x, ba);
                    fma2(acc[0][2*j + 1], qq.y, ba);
                    fma2(acc[1][2*j],     qq.x, bb);
                    fma2(acc[1][2*j + 1], qq.y, bb);
                }
            }
        }
        bool mA = (mrow[kA] != 0.f), mB = (mrow[kA + 512] != 0.f);
        #pragma unroll
        for (int qp = 0; qp < 8; qp++) {
            float2 a = unpack2(acc[0][qp]);
            float2 c = unpack2(acc[1][qp]);
            sS[(2*qp)     * T_ + kA]       = mA ? NEGINF : a.x * SCALE_INV;
            sS[(2*qp + 1) * T_ + kA]       = mA ? NEGINF : a.y * SCALE_INV;
            sS[(2*qp)     * T_ + kA + 512] = mB ? NEGINF : c.x * SCALE_INV;
            sS[(2*qp + 1) * T_ + kA + 512] = mB ? NEGINF : c.y * SCALE_INV;
        }
    }
    __syncthreads();

    // ---- phase 2: sparsemax per row (Michelot exact projection), 1 warp / row ----
    {
        int warp = tid >> 5, lane = tid & 31;   // warp == q row (16 warps)
        float* row = sS + warp * T_;

        float s = 0.f;
        for (int i = lane; i < T_; i += 32) s += row[i];
        s = wsum(s);
        float tau = (s - 1.0f) * (1.0f / T_);

        #pragma unroll 1
        for (int it = 0; it < 64; it++) {
            float ss = 0.f; int c = 0;
            for (int i = lane; i < T_; i += 32) {
                float z = row[i];
                if (z > tau) { ss += z; c++; }
            }
            ss = wsum(ss); c = wsumi(c);
            float nt = (ss - 1.0f) / (float)c;
            if (!(nt > tau)) break;
            tau = nt;
        }

        // write p and compact nonzero (idx, p)
        int cnt = 0;
        for (int i = lane; i < T_; i += 32) {
            float p = row[i] - tau;
            bool nz = (p > 0.f);
            p = nz ? p : 0.f;
            row[i] = p;
            unsigned m = __ballot_sync(0xffffffffu, nz);
            int pos = cnt + __popc(m & ((1u << lane) - 1u));
            if (nz && pos < SMAX) { sP[warp * SMAX + pos] = p; sIdx[warp * SMAX + pos] = i; }
            cnt += __popc(m);
        }
        if (lane == 0) sCnt[warp] = cnt;
    }
    __syncthreads();

    // ---- phase 3: out = A @ V over compacted support (typ. ~30 keys/row) ----
    {
        int d  = tid & 63;
        int qg = tid >> 6;                       // 0..7, two queries each
        const float* Vd = g_V + bh * T_ * HD_ + d;
        #pragma unroll
        for (int qq = 0; qq < 2; qq++) {
            int q = qg * 2 + qq;
            int cnt = sCnt[q];
            float acc = 0.f;
            if (cnt <= SMAX) {
                const float* pp = sP + q * SMAX;
                const int*   ii = sIdx + q * SMAX;
                for (int j = 0; j < cnt; j++)
                    acc += pp[j] * Vd[ii[j] * HD_];
            } else {
                const float* row = sS + q * T_;   // exact dense fallback
                for (int k = 0; k < T_; k++) {
                    float p = row[k];
                    if (p > 0.f) acc += p * Vd[k * HD_];
                }
            }
            g_attn[(b * T_ + q0 + q) * D_ + h * HD_ + d] = acc;
        }
    }
}

// ---------------- LayerNorm (1 warp per 256-elem row) ----------------
__global__ __launch_bounds__(256)
void ln_kernel(const float* __restrict__ gamma,
               const float* __restrict__ beta,
               float* __restrict__ out)
{
    int warp = threadIdx.x >> 5, lane = threadIdx.x & 31;
    int row  = blockIdx.x * 8 + warp;
    const float* y = g_y + row * 256;
    float v[8];
    float s = 0.f;
    #pragma unroll
    for (int i = 0; i < 8; i++) { v[i] = y[lane + i * 32]; s += v[i]; }
    s = wsum(s);
    float mu = s * (1.0f / 256.0f);
    float vs = 0.f;
    #pragma unroll
    for (int i = 0; i < 8; i++) { float d = v[i] - mu; vs += d * d; }
    vs = wsum(vs);
    float rstd = rsqrtf(vs * (1.0f / 256.0f) + 1e-5f);
    #pragma unroll
    for (int i = 0; i < 8; i++) {
        int c = lane + i * 32;
        out[row * 256 + c] = (v[i] - mu) * rstd * gamma[c] + beta[c];
    }
}

// ---------------- launch ----------------
extern "C" void kernel_launch(void* const* d_in, const int* in_sizes, int n_in,
                              void* d_out, int out_size)
{
    const float* x     = (const float*)d_in[0];
    const void*  mask  = d_in[1];
    const float* Wq    = (const float*)d_in[2];
    const float* Wk    = (const float*)d_in[3];
    const float* Wv    = (const float*)d_in[4];
    const float* Wo    = (const float*)d_in[5];
    const float* gamma = (const float*)d_in[6];
    const float* beta  = (const float*)d_in[7];
    float* out = (float*)d_out;

    cudaFuncSetAttribute(attn_kernel,
                         cudaFuncAttributeMaxDynamicSharedMemorySize, ATTN_SMEM);

    detect_mask_kernel<<<1, 256>>>((const unsigned int*)mask);
    expand_mask_kernel<<<(NTOK_ + 255) / 256, 256>>>(mask);

    dim3 ggrid(NTOK_ / 64, D_ / 64, 3);
    qkv_gemm_kernel<<<ggrid, 256>>>(x, Wq, Wk, Wv);

    attn_kernel<<<dim3(T_ / QT, BH_), 512, ATTN_SMEM>>>();

    oproj_gemm_kernel<<<dim3(NTOK_ / 64, D_ / 64), 256>>>(Wo, x);

    ln_kernel<<<NTOK_ / 8, 256>>>(gamma, beta, out);
}

// round 6
// speedup vs baseline: 2.5584x; 2.5584x over previous
#include <cuda_runtime.h>

// ---------------- problem constants ----------------
constexpr int B_   = 8;
constexpr int T_   = 2048;
constexpr int D_   = 256;
constexpr int H_   = 4;
constexpr int HD_  = 64;
constexpr int BH_  = B_ * H_;     // 32
constexpr int NTOK_ = B_ * T_;    // 16384
constexpr float SCALE_INV = 0.125f;   // 1/sqrt(64)
constexpr float NEGINF = -1e9f;

constexpr int QT   = 16;    // queries per attention block
constexpr int SMAX = 512;   // compacted support capacity per row (dense fallback if exceeded)

// ---------------- scratch (device globals; no allocation allowed) ----------------
__device__ float g_Q[BH_ * T_ * HD_];     // [bh][t][hd]
__device__ float g_K[BH_ * T_ * HD_];
__device__ float g_V[BH_ * T_ * HD_];
__device__ float g_attn[NTOK_ * D_];      // [token][feature] (b,t,h,hd)
__device__ float g_y[NTOK_ * D_];         // pre-LN output
__device__ float g_maskf[NTOK_];          // 0.0 / 1.0
__device__ int   g_flag;                  // mask dtype: 0=u8, 1=i32, 2=f32

// ---------------- helpers ----------------
__device__ __forceinline__ float wsum(float v) {
    #pragma unroll
    for (int o = 16; o > 0; o >>= 1) v += __shfl_xor_sync(0xffffffffu, v, o);
    return v;
}
__device__ __forceinline__ int wsumi(int v) {
    #pragma unroll
    for (int o = 16; o > 0; o >>= 1) v += __shfl_xor_sync(0xffffffffu, v, o);
    return v;
}

// ---- tf32 tensor-core mma (m16n8k8), fp32 accumulate ----
__device__ __forceinline__ unsigned cvt_tf32(float x) {
    unsigned r;
    asm("cvt.rna.tf32.f32 %0, %1;" : "=r"(r) : "f"(x));
    return r;
}
__device__ __forceinline__ void mma_tf32(float* c, const unsigned* a,
                                         unsigned b0, unsigned b1) {
    asm volatile(
        "mma.sync.aligned.m16n8k8.row.col.f32.tf32.tf32.f32 "
        "{%0,%1,%2,%3}, {%4,%5,%6,%7}, {%8,%9}, {%0,%1,%2,%3};"
        : "+f"(c[0]), "+f"(c[1]), "+f"(c[2]), "+f"(c[3])
        : "r"(a[0]), "r"(a[1]), "r"(a[2]), "r"(a[3]), "r"(b0), "r"(b1));
}

// ---------------- mask dtype detection + normalization ----------------
// Word signatures: f32 one = 0x3f800000; i32 words are 0/1; u8-packed words
// contain bytes at offsets 1..3 -> values > 1. Mutually exclusive w.h.p.
__global__ void detect_mask_kernel(const unsigned int* __restrict__ m) {
    __shared__ int sawF, sawBig;
    if (threadIdx.x == 0) { sawF = 0; sawBig = 0; }
    __syncthreads();
    int f = 0, big = 0;
    for (int i = threadIdx.x; i < 4096; i += blockDim.x) {
        unsigned int w = m[i];
        if (w == 0x3f800000u) f = 1;
        else if (w > 1u) big = 1;
    }
    if (f)   atomicOr(&sawF, 1);
    if (big) atomicOr(&sawBig, 1);
    __syncthreads();
    if (threadIdx.x == 0) g_flag = sawF ? 2 : (sawBig ? 0 : 1);
}

__global__ void expand_mask_kernel(const void* __restrict__ m) {
    int i = blockIdx.x * blockDim.x + threadIdx.x;
    if (i >= NTOK_) return;
    int mode = g_flag;
    int v;
    if (mode == 0)      v = (((const unsigned char*)m)[i] != 0);
    else if (mode == 1) v = (((const int*)m)[i] != 0);
    else                v = (((const float*)m)[i] != 0.0f);
    g_maskf[i] = v ? 1.0f : 0.0f;
}

// ---------------- QKV GEMM (fused via blockIdx.z): C = x @ W^T -> head layout ----------
__global__ __launch_bounds__(256, 2)
void qkv_gemm_kernel(const float* __restrict__ A,
                     const float* __restrict__ Wq,
                     const float* __restrict__ Wk,
                     const float* __restrict__ Wv)
{
    __shared__ float sA[16 * 64];   // [k][m]
    __shared__ float sB[16 * 64];   // [k][n]

    const float* W   = (blockIdx.z == 0) ? Wq : (blockIdx.z == 1) ? Wk : Wv;
    float*       dst = (blockIdx.z == 0) ? g_Q : (blockIdx.z == 1) ? g_K : g_V;

    int t  = threadIdx.x;           // 256 threads
    int tx = t & 15, ty = t >> 4;
    int m0 = blockIdx.x * 64, n0 = blockIdx.y * 64;
    int lr = t >> 2, lk = t & 3;    // loader: row 0..63, k-quad 0..3

    float acc[4][4] = {};
    for (int k0 = 0; k0 < 256; k0 += 16) {
        float4 av = *(const float4*)&A[(m0 + lr) * 256 + k0 + lk * 4];
        float4 bv = *(const float4*)&W[(n0 + lr) * 256 + k0 + lk * 4];
        __syncthreads();
        sA[(lk*4+0)*64 + lr] = av.x; sA[(lk*4+1)*64 + lr] = av.y;
        sA[(lk*4+2)*64 + lr] = av.z; sA[(lk*4+3)*64 + lr] = av.w;
        sB[(lk*4+0)*64 + lr] = bv.x; sB[(lk*4+1)*64 + lr] = bv.y;
        sB[(lk*4+2)*64 + lr] = bv.z; sB[(lk*4+3)*64 + lr] = bv.w;
        __syncthreads();
        #pragma unroll
        for (int kk = 0; kk < 16; kk++) {
            float4 a4 = *(const float4*)&sA[kk * 64 + ty * 4];
            float4 b4 = *(const float4*)&sB[kk * 64 + tx * 4];
            float ar[4] = {a4.x, a4.y, a4.z, a4.w};
            float br[4] = {b4.x, b4.y, b4.z, b4.w};
            #pragma unroll
            for (int i = 0; i < 4; i++)
                #pragma unroll
                for (int j = 0; j < 4; j++)
                    acc[i][j] += ar[i] * br[j];
        }
    }

    #pragma unroll
    for (int i = 0; i < 4; i++) {
        int gm = m0 + ty * 4 + i;
        int b  = gm >> 11, tl = gm & 2047;
        #pragma unroll
        for (int j = 0; j < 4; j++) {
            int gn = n0 + tx * 4 + j;
            int h = gn >> 6, hd = gn & 63;
            dst[((b * H_ + h) * T_ + tl) * HD_ + hd] = acc[i][j];
        }
    }
}

// ---------------- out-proj GEMM: g_y = g_attn @ Wo^T + resid ----------------
__global__ __launch_bounds__(256, 2)
void oproj_gemm_kernel(const float* __restrict__ W,
                       const float* __restrict__ resid)
{
    __shared__ float sA[16 * 64];
    __shared__ float sB[16 * 64];
    const float* A = g_attn;

    int t  = threadIdx.x;
    int tx = t & 15, ty = t >> 4;
    int m0 = blockIdx.x * 64, n0 = blockIdx.y * 64;
    int lr = t >> 2, lk = t & 3;

    float acc[4][4] = {};
    for (int k0 = 0; k0 < 256; k0 += 16) {
        float4 av = *(const float4*)&A[(m0 + lr) * 256 + k0 + lk * 4];
        float4 bv = *(const float4*)&W[(n0 + lr) * 256 + k0 + lk * 4];
        __syncthreads();
        sA[(lk*4+0)*64 + lr] = av.x; sA[(lk*4+1)*64 + lr] = av.y;
        sA[(lk*4+2)*64 + lr] = av.z; sA[(lk*4+3)*64 + lr] = av.w;
        sB[(lk*4+0)*64 + lr] = bv.x; sB[(lk*4+1)*64 + lr] = bv.y;
        sB[(lk*4+2)*64 + lr] = bv.z; sB[(lk*4+3)*64 + lr] = bv.w;
        __syncthreads();
        #pragma unroll
        for (int kk = 0; kk < 16; kk++) {
            float4 a4 = *(const float4*)&sA[kk * 64 + ty * 4];
            float4 b4 = *(const float4*)&sB[kk * 64 + tx * 4];
            float ar[4] = {a4.x, a4.y, a4.z, a4.w};
            float br[4] = {b4.x, b4.y, b4.z, b4.w};
            #pragma unroll
            for (int i = 0; i < 4; i++)
                #pragma unroll
                for (int j = 0; j < 4; j++)
                    acc[i][j] += ar[i] * br[j];
        }
    }

    #pragma unroll
    for (int i = 0; i < 4; i++) {
        int gm = m0 + ty * 4 + i;
        #pragma unroll
        for (int j = 0; j < 4; j++) {
            int gn = n0 + tx * 4 + j;
            g_y[gm * 256 + gn] = acc[i][j] + resid[gm * 256 + gn];
        }
    }
}

// ---------------- fused attention: tf32-MMA scores -> sparsemax -> sparse A@V ----------
// grid (T/QT, BH), 512 threads (16 warps). Each warp owns 128 keys of the
// 16-query x 2048-key score tile; scores stay SMEM-resident.
constexpr int ATTN_SMEM =
    (QT * T_            /* sS   */
   + QT * HD_           /* sQ   */
   + T_                 /* sM   */
   + QT * SMAX) * 4     /* sP   */
   + QT * SMAX * 4      /* sIdx */
   + QT * 4;            /* sCnt */

__global__ __launch_bounds__(512, 1)
void attn_kernel() {
    extern __shared__ float smem[];
    float* sS   = smem;                        // [QT][T]  scores -> p
    float* sQ   = sS + QT * T_;                // [QT][HD] fp32 Q tile
    float* sM   = sQ + QT * HD_;               // [T] mask
    float* sP   = sM + T_;                     // [QT][SMAX] compacted p
    int*   sIdx = (int*)(sP + QT * SMAX);      // [QT][SMAX] compacted k
    int*   sCnt = sIdx + QT * SMAX;            // [QT]

    const int tid  = threadIdx.x;
    const int warp = tid >> 5, lane = tid & 31;
    const int bh   = blockIdx.y;
    const int b    = bh >> 2;
    const int h    = bh & 3;
    const int q0   = blockIdx.x * QT;

    // ---- load Q tile + mask row ----
    const float* Qbase = g_Q + (bh * T_ + q0) * HD_;
    const float* mrow  = g_maskf + b * T_;
    for (int i = tid; i < QT * HD_; i += 512) sQ[i] = Qbase[i];
    for (int i = tid; i < T_; i += 512)       sM[i] = mrow[i];
    __syncthreads();

    // ---- phase 1: scores = QK^T/8 via mma.sync tf32 ----
    {
        const int g = lane >> 2;        // groupID 0..7
        const int t = lane & 3;         // thread-in-group

        // A fragments: Q[16][64] -> 8 k-steps x 4 regs (preloaded once)
        unsigned afr[8][4];
        #pragma unroll
        for (int s = 0; s < 8; s++) {
            afr[s][0] = cvt_tf32(sQ[g        * HD_ + s * 8 + t]);
            afr[s][1] = cvt_tf32(sQ[(g + 8)  * HD_ + s * 8 + t]);
            afr[s][2] = cvt_tf32(sQ[g        * HD_ + s * 8 + t + 4]);
            afr[s][3] = cvt_tf32(sQ[(g + 8)  * HD_ + s * 8 + t + 4]);
        }

        const float* Kbase = g_K + bh * T_ * HD_;
        const int kwarp = warp * 128;
        #pragma unroll 1
        for (int nt = 0; nt < 16; nt++) {
            int kb = kwarp + nt * 8;
            const float* Krow = Kbase + (kb + g) * HD_;   // B col n = g
            float c[4] = {0.f, 0.f, 0.f, 0.f};
            #pragma unroll
            for (int s = 0; s < 8; s++) {
                unsigned b0 = cvt_tf32(Krow[s * 8 + t]);
                unsigned b1 = cvt_tf32(Krow[s * 8 + t + 4]);
                mma_tf32(c, afr[s], b0, b1);
            }
            // C layout: c0=(g, 2t) c1=(g, 2t+1) c2=(g+8, 2t) c3=(g+8, 2t+1)
            float2 mk = *(const float2*)&sM[kb + 2 * t];
            float o0 = (mk.x != 0.f) ? NEGINF : c[0] * SCALE_INV;
            float o1 = (mk.y != 0.f) ? NEGINF : c[1] * SCALE_INV;
            float o2 = (mk.x != 0.f) ? NEGINF : c[2] * SCALE_INV;
            float o3 = (mk.y != 0.f) ? NEGINF : c[3] * SCALE_INV;
            *(float2*)&sS[g       * T_ + kb + 2 * t] = make_float2(o0, o1);
            *(float2*)&sS[(g + 8) * T_ + kb + 2 * t] = make_float2(o2, o3);
        }
    }
    __syncthreads();

    // ---- phase 2: sparsemax per row (Michelot exact projection), 1 warp / row ----
    {
        float* row = sS + warp * T_;

        float s = 0.f;
        for (int i = lane; i < T_; i += 32) s += row[i];
        s = wsum(s);
        float tau = (s - 1.0f) * (1.0f / T_);

        #pragma unroll 1
        for (int it = 0; it < 64; it++) {
            float ss = 0.f; int c = 0;
            for (int i = lane; i < T_; i += 32) {
                float z = row[i];
                if (z > tau) { ss += z; c++; }
            }
            ss = wsum(ss); c = wsumi(c);
            float nt = (ss - 1.0f) / (float)c;
            if (!(nt > tau)) break;
            tau = nt;
        }

        // write p and compact nonzero (idx, p)
        int cnt = 0;
        for (int i = lane; i < T_; i += 32) {
            float p = row[i] - tau;
            bool nz = (p > 0.f);
            p = nz ? p : 0.f;
            row[i] = p;
            unsigned m = __ballot_sync(0xffffffffu, nz);
            int pos = cnt + __popc(m & ((1u << lane) - 1u));
            if (nz && pos < SMAX) { sP[warp * SMAX + pos] = p; sIdx[warp * SMAX + pos] = i; }
            cnt += __popc(m);
        }
        if (lane == 0) sCnt[warp] = cnt;
    }
    __syncthreads();

    // ---- phase 3: out = A @ V over compacted support ----
    {
        int d  = tid & 63;
        int qg = tid >> 6;                       // 0..7, two queries each
        const float* Vd = g_V + bh * T_ * HD_ + d;
        #pragma unroll
        for (int qq = 0; qq < 2; qq++) {
            int q = qg * 2 + qq;
            int cnt = sCnt[q];
            float acc = 0.f;
            if (cnt <= SMAX) {
                const float* pp = sP + q * SMAX;
                const int*   ii = sIdx + q * SMAX;
                for (int j = 0; j < cnt; j++)
                    acc += pp[j] * Vd[ii[j] * HD_];
            } else {
                const float* row = sS + q * T_;   // exact dense fallback
                for (int k = 0; k < T_; k++) {
                    float p = row[k];
                    if (p > 0.f) acc += p * Vd[k * HD_];
                }
            }
            g_attn[(b * T_ + q0 + q) * D_ + h * HD_ + d] = acc;
        }
    }
}

// ---------------- LayerNorm (1 warp per 256-elem row) ----------------
__global__ __launch_bounds__(256)
void ln_kernel(const float* __restrict__ gamma,
               const float* __restrict__ beta,
               float* __restrict__ out)
{
    int warp = threadIdx.x >> 5, lane = threadIdx.x & 31;
    int row  = blockIdx.x * 8 + warp;
    const float* y = g_y + row * 256;
    float v[8];
    float s = 0.f;
    #pragma unroll
    for (int i = 0; i < 8; i++) { v[i] = y[lane + i * 32]; s += v[i]; }
    s = wsum(s);
    float mu = s * (1.0f / 256.0f);
    float vs = 0.f;
    #pragma unroll
    for (int i = 0; i < 8; i++) { float d = v[i] - mu; vs += d * d; }
    vs = wsum(vs);
    float rstd = rsqrtf(vs * (1.0f / 256.0f) + 1e-5f);
    #pragma unroll
    for (int i = 0; i < 8; i++) {
        int c = lane + i * 32;
        out[row * 256 + c] = (v[i] - mu) * rstd * gamma[c] + beta[c];
    }
}

// ---------------- launch ----------------
extern "C" void kernel_launch(void* const* d_in, const int* in_sizes, int n_in,
                              void* d_out, int out_size)
{
    const float* x     = (const float*)d_in[0];
    const void*  mask  = d_in[1];
    const float* Wq    = (const float*)d_in[2];
    const float* Wk    = (const float*)d_in[3];
    const float* Wv    = (const float*)d_in[4];
    const float* Wo    = (const float*)d_in[5];
    const float* gamma = (const float*)d_in[6];
    const float* beta  = (const float*)d_in[7];
    float* out = (float*)d_out;

    cudaFuncSetAttribute(attn_kernel,
                         cudaFuncAttributeMaxDynamicSharedMemorySize, ATTN_SMEM);

    detect_mask_kernel<<<1, 256>>>((const unsigned int*)mask);
    expand_mask_kernel<<<(NTOK_ + 255) / 256, 256>>>(mask);

    dim3 ggrid(NTOK_ / 64, D_ / 64, 3);
    qkv_gemm_kernel<<<ggrid, 256>>>(x, Wq, Wk, Wv);

    attn_kernel<<<dim3(T_ / QT, BH_), 512, ATTN_SMEM>>>();

    oproj_gemm_kernel<<<dim3(NTOK_ / 64, D_ / 64), 256>>>(Wo, x);

    ln_kernel<<<NTOK_ / 8, 256>>>(gamma, beta, out);
}